// round 7
// baseline (speedup 1.0000x reference)
#include <cuda_runtime.h>
#include <cuda_fp16.h>
#include <math.h>
#include <stdint.h>

#define NN   50000
#define BB   50
#define NPGc 1000
#define EE   300000
#define HH   256
#define KSEL 500
#define SCB  196           // ceil(NN/256) scan blocks

// ---------------- scratch (static device globals; no allocation) ----------------
__device__ __half d_h1h[NN * HH];    // layer1 output, fp16
__device__ __half d_gh [NN * HH];    // aggregated h1, fp16 (GEMM A)
__device__ __half d_w2t[HH * HH];    // W2^T [n][k], fp16 (GEMM B)
__device__ float  d_h  [NN * HH];    // layer2 output, fp32
__device__ int    d_indeg[NN];
__device__ int    d_rowptr[NN + 1];
__device__ int    d_fill[NN];
__device__ int    d_col[EE];
__device__ float  d_dinv[NN];
__device__ float  d_r[NN];
__device__ float  d_root[NN];
__device__ unsigned long long d_state[SCB];   // lookback scan state: flag<<32 | value

// ---------------- helpers ----------------
__device__ __forceinline__ uint32_t smem_u32(const void* p) {
    uint32_t a;
    asm("{ .reg .u64 t; cvta.to.shared.u64 t, %1; cvt.u32.u64 %0, t; }" : "=r"(a) : "l"(p));
    return a;
}
__device__ __forceinline__ void cpa16(uint32_t dst, const void* src, int srcsz) {
    asm volatile("cp.async.ca.shared.global [%0], [%1], 16, %2;"
                 :: "r"(dst), "l"(src), "r"(srcsz));
}
#define CPA_COMMIT() asm volatile("cp.async.commit_group;" ::: "memory")
#define CPA_WAIT(n)  asm volatile("cp.async.wait_group %0;" :: "n"(n) : "memory")

// ---------------- init ----------------
__global__ void k_zero() {
    int i = blockIdx.x * blockDim.x + threadIdx.x;
    if (i < NN) d_indeg[i] = 0;
    if (i < SCB) d_state[i] = 0ull;
}

// ---------------- histogram + W2 transpose fold ----------------
__global__ void k_hist(const int* __restrict__ dst, const float* __restrict__ W2) {
    int t = threadIdx.x;
    int i = blockIdx.x * blockDim.x + t;
    if (i < EE) atomicAdd(&d_indeg[dst[i]], 1);
    int n = blockIdx.x;
    if (n < HH) d_w2t[n * HH + t] = __float2half_rn(W2[t * HH + n]);
}

// ---------------- single-pass decoupled-lookback exclusive scan ----------------
// Also: dinv = rsqrt(indeg+1), zero d_fill / d_r / d_root, rowptr[NN] = EE.
__global__ __launch_bounds__(256) void k_scan() {
    __shared__ int ws[8];
    __shared__ int s_prefix;
    int t = threadIdx.x, lane = t & 31, wid = t >> 5;
    int b = blockIdx.x;
    int i = b * 256 + t;
    int v = (i < NN) ? d_indeg[i] : 0;
    // block-local inclusive scan
    int s = v;
    #pragma unroll
    for (int o = 1; o < 32; o <<= 1) {
        int n = __shfl_up_sync(0xffffffffu, s, o);
        if (lane >= o) s += n;
    }
    if (lane == 31) ws[wid] = s;
    __syncthreads();
    if (wid == 0 && lane < 8) {
        int x = ws[lane];
        #pragma unroll
        for (int o = 1; o < 8; o <<= 1) {
            int n = __shfl_up_sync(0xffu, x, o);
            if (lane >= o) x += n;
        }
        ws[lane] = x;
    }
    __syncthreads();
    int lexcl = s - v + (wid > 0 ? ws[wid - 1] : 0);
    int total = ws[7];

    if (t == 0) {
        if (b == 0) {
            *(volatile unsigned long long*)&d_state[0] =
                (2ull << 32) | (unsigned long long)(unsigned)total;
            s_prefix = 0;
        } else {
            // publish aggregate
            *(volatile unsigned long long*)&d_state[b] =
                (1ull << 32) | (unsigned long long)(unsigned)total;
            // lookback
            int sum = 0;
            int j = b - 1;
            while (1) {
                unsigned long long st;
                do { st = *(volatile unsigned long long*)&d_state[j]; } while ((st >> 32) == 0ull);
                sum += (int)(unsigned)st;
                if ((st >> 32) == 2ull) break;
                j--;
            }
            // publish inclusive
            *(volatile unsigned long long*)&d_state[b] =
                (2ull << 32) | (unsigned long long)(unsigned)(sum + total);
            s_prefix = sum;
        }
    }
    __syncthreads();
    int prefix = s_prefix;
    if (i < NN) {
        d_rowptr[i] = prefix + lexcl;
        d_dinv[i]   = rsqrtf((float)(v + 1));
        d_fill[i]   = 0;
        d_r[i]      = 0.f;
        d_root[i]   = 0.f;
    }
    if (b == SCB - 1 && t == 0) d_rowptr[NN] = EE;
}

__global__ void k_scatter(const int* __restrict__ src, const int* __restrict__ dst) {
    int i = blockIdx.x * blockDim.x + threadIdx.x;
    if (i < EE) {
        int d = dst[i];
        int p = d_rowptr[d] + atomicAdd(&d_fill[d], 1);
        d_col[p] = src[i];
    }
}

// ---------------- layer 1: onehot-gather GCN conv, lane-parallel edge prefetch ----------------
__global__ __launch_bounds__(256) void k_layer1(const int* __restrict__ x,
                                                const float* __restrict__ W1,
                                                const float* __restrict__ b1) {
    int node = (blockIdx.x * blockDim.x + threadIdx.x) >> 5;
    int lane = threadIdx.x & 31;
    if (node >= NN) return;
    float dd = d_dinv[node];
    float a[8];
    {
        const float4* p = (const float4*)(W1 + (size_t)x[node] * HH) + lane * 2;
        float4 v0 = p[0], v1 = p[1];
        a[0] = dd * v0.x; a[1] = dd * v0.y; a[2] = dd * v0.z; a[3] = dd * v0.w;
        a[4] = dd * v1.x; a[5] = dd * v1.y; a[6] = dd * v1.z; a[7] = dd * v1.w;
    }
    int beg = d_rowptr[node], end = d_rowptr[node + 1];
    for (int eb = beg; eb < end; eb += 32) {
        int n = min(32, end - eb);
        int si = 0, xi = 0; float wi = 0.f;
        if (lane < n) { si = d_col[eb + lane]; wi = d_dinv[si]; xi = x[si]; }
        for (int e = 0; e < n; e++) {
            int   xe = __shfl_sync(0xffffffffu, xi, e);
            float we = __shfl_sync(0xffffffffu, wi, e);
            const float4* p = (const float4*)(W1 + (size_t)xe * HH) + lane * 2;
            float4 v0 = p[0], v1 = p[1];
            a[0] += we * v0.x; a[1] += we * v0.y; a[2] += we * v0.z; a[3] += we * v0.w;
            a[4] += we * v1.x; a[5] += we * v1.y; a[6] += we * v1.z; a[7] += we * v1.w;
        }
    }
    const float4* b4 = (const float4*)b1 + lane * 2;
    float4 c0 = b4[0], c1 = b4[1];
    float o[8];
    o[0] = fmaxf(dd * a[0] + c0.x, 0.f); o[1] = fmaxf(dd * a[1] + c0.y, 0.f);
    o[2] = fmaxf(dd * a[2] + c0.z, 0.f); o[3] = fmaxf(dd * a[3] + c0.w, 0.f);
    o[4] = fmaxf(dd * a[4] + c1.x, 0.f); o[5] = fmaxf(dd * a[5] + c1.y, 0.f);
    o[6] = fmaxf(dd * a[6] + c1.z, 0.f); o[7] = fmaxf(dd * a[7] + c1.w, 0.f);
    uint4 pk;
    ((__half2*)&pk)[0] = __floats2half2_rn(o[0], o[1]);
    ((__half2*)&pk)[1] = __floats2half2_rn(o[2], o[3]);
    ((__half2*)&pk)[2] = __floats2half2_rn(o[4], o[5]);
    ((__half2*)&pk)[3] = __floats2half2_rn(o[6], o[7]);
    ((uint4*)(d_h1h + (size_t)node * HH))[lane] = pk;
}

// ---------------- layer 2 aggregation, smem-tiled per (graph, 64-feature slice) ----------------
// Block (fs, g): load h1[g*1000 .. , fs*64 .. fs*64+64) into smem (125 KB),
// then dst-partitioned warps walk CSR; lane = half2 feature pair (conflict-free LDS).
#define AGG_SMEM (NPGc * 64 * 2)

__global__ __launch_bounds__(512) void k_agg() {
    extern __shared__ __align__(16) char asm_[];
    uint32_t* sin_u = (uint32_t*)asm_;           // [1000][32] uints (64 halves/row)
    int t = threadIdx.x, lane = t & 31, wid = t >> 5;
    int g0 = blockIdx.y * NPGc;
    int fo = blockIdx.x * 64;

    // load phase: 8000 uint4, coalesced
    for (int i = t; i < NPGc * 8; i += 512) {
        int row = i >> 3, q = i & 7;
        ((uint4*)asm_)[i] = ((const uint4*)(d_h1h + (size_t)(g0 + row) * HH + fo))[q];
    }
    __syncthreads();

    // edge phase: warp owns nodes [wid*63, wid*63+63)
    int n0 = wid * 63, n1 = min(n0 + 63, NPGc);
    for (int ni = n0; ni < n1; ni++) {
        int n = g0 + ni;
        float ddn = d_dinv[n];
        uint32_t v = sin_u[ni * 32 + lane];
        float2 f = __half22float2(*(__half2*)&v);
        float2 acc = make_float2(ddn * f.x, ddn * f.y);
        int e0 = d_rowptr[n], e1 = d_rowptr[n + 1];
        for (int eb = e0; eb < e1; eb += 32) {
            int m = min(32, e1 - eb);
            int sl = 0; float w = 0.f;
            if (lane < m) {
                int s = d_col[eb + lane];
                w = d_dinv[s];
                sl = s - g0;
            }
            for (int e = 0; e < m; e++) {
                int   sle = __shfl_sync(0xffffffffu, sl, e);
                float we  = __shfl_sync(0xffffffffu, w, e);
                uint32_t vs = sin_u[sle * 32 + lane];
                float2 fs = __half22float2(*(__half2*)&vs);
                acc.x += we * fs.x;
                acc.y += we * fs.y;
            }
        }
        __half2 hv = __floats2half2_rn(ddn * acc.x, ddn * acc.y);
        ((uint32_t*)(d_gh + (size_t)n * HH + fo))[lane] = *(uint32_t*)&hv;
    }
}

// ---------------- GEMM: h = relu(g @ W2 + b2) via fp16 mma m16n8k16, fused scorer ----------------
#define SROWH 40
#define STGH  (128 * SROWH)
#define GEMM_SMEM (4 * STGH * 2 + 3 * HH * 4)

__global__ __launch_bounds__(256) void k_gemm(const float* __restrict__ b2,
                                              const float* __restrict__ Wrel,
                                              const float* __restrict__ Wroot) {
    extern __shared__ __align__(16) char smc[];
    __half* sA = (__half*)smc;
    __half* sB = sA + 2 * STGH;
    float*  b2s = (float*)(sB + 2 * STGH);
    float*  wrs = b2s + HH;
    float*  wos = wrs + HH;
    uint32_t sA_u = smem_u32(sA), sB_u = smem_u32(sB);

    int tid = threadIdx.x, lane = tid & 31, warpId = tid >> 5;
    int warp_m = warpId & 1, warp_n = warpId >> 1;
    int rowBase = blockIdx.x * 128;
    int colBase = blockIdx.y * 128;

    for (int i = tid; i < HH; i += 256) { b2s[i] = b2[i]; wrs[i] = Wrel[i]; wos[i] = Wroot[i]; }

    float c[4][4][4];
    #pragma unroll
    for (int mt = 0; mt < 4; mt++)
        #pragma unroll
        for (int nt = 0; nt < 4; nt++)
            #pragma unroll
            for (int q = 0; q < 4; q++) c[mt][nt][q] = 0.f;

    int cprow = tid >> 1, cpc = (tid & 1) * 2;
    #define PREFETCH(s) do {                                                         \
        int buf = (s) & 1;                                                           \
        int gr = rowBase + cprow;                                                    \
        int sz = (gr < NN) ? 16 : 0;                                                 \
        int grc = (gr < NN) ? gr : 0;                                                \
        int nrow = colBase + cprow;                                                  \
        _Pragma("unroll")                                                            \
        for (int h = 0; h < 2; h++) {                                                \
            int cc = cpc + h;                                                        \
            cpa16(sA_u + (uint32_t)(buf * STGH + cprow * SROWH + cc * 8) * 2,        \
                  d_gh + (size_t)grc * HH + (s) * 32 + cc * 8, sz);                  \
            cpa16(sB_u + (uint32_t)(buf * STGH + cprow * SROWH + cc * 8) * 2,        \
                  d_w2t + (size_t)nrow * HH + (s) * 32 + cc * 8, 16);                \
        }                                                                            \
    } while (0)

    PREFETCH(0); CPA_COMMIT();

    int fc = lane & 3, fr = lane >> 2;
    for (int s = 0; s < 8; s++) {
        if (s < 7) { PREFETCH(s + 1); CPA_COMMIT(); CPA_WAIT(1); }
        else       { CPA_WAIT(0); }
        __syncthreads();
        const __half* A = sA + (s & 1) * STGH;
        const __half* B = sB + (s & 1) * STGH;
        #pragma unroll
        for (int ks = 0; ks < 2; ks++) {
            uint32_t a0[4], a1[4], a2[4], a3[4], b0[4], b1[4];
            #pragma unroll
            for (int mt = 0; mt < 4; mt++) {
                int mr = warp_m * 64 + mt * 16 + fr;
                const __half* pa  = A + mr * SROWH + ks * 16 + fc * 2;
                const __half* pa8 = pa + 8 * SROWH;
                a0[mt] = *(const uint32_t*)pa;
                a2[mt] = *(const uint32_t*)(pa + 8);
                a1[mt] = *(const uint32_t*)pa8;
                a3[mt] = *(const uint32_t*)(pa8 + 8);
            }
            #pragma unroll
            for (int nt = 0; nt < 4; nt++) {
                int nr = warp_n * 32 + nt * 8 + fr;
                const __half* pb = B + nr * SROWH + ks * 16 + fc * 2;
                b0[nt] = *(const uint32_t*)pb;
                b1[nt] = *(const uint32_t*)(pb + 8);
            }
            #pragma unroll
            for (int mt = 0; mt < 4; mt++)
                #pragma unroll
                for (int nt = 0; nt < 4; nt++) {
                    asm volatile(
                        "mma.sync.aligned.m16n8k16.row.col.f32.f16.f16.f32 "
                        "{%0,%1,%2,%3}, {%4,%5,%6,%7}, {%8,%9}, {%0,%1,%2,%3};"
                        : "+f"(c[mt][nt][0]), "+f"(c[mt][nt][1]),
                          "+f"(c[mt][nt][2]), "+f"(c[mt][nt][3])
                        : "r"(a0[mt]), "r"(a1[mt]), "r"(a2[mt]), "r"(a3[mt]),
                          "r"(b0[nt]), "r"(b1[nt]));
                }
        }
        __syncthreads();
    }

    #pragma unroll
    for (int mt = 0; mt < 4; mt++) {
        int r0 = rowBase + warp_m * 64 + mt * 16 + (lane >> 2);
        int r1 = r0 + 8;
        float pr0 = 0.f, po0 = 0.f, pr1 = 0.f, po1 = 0.f;
        #pragma unroll
        for (int nt = 0; nt < 4; nt++) {
            int col = colBase + warp_n * 32 + nt * 8 + 2 * (lane & 3);
            float bx = b2s[col], by = b2s[col + 1];
            float h00 = fmaxf(c[mt][nt][0] + bx, 0.f);
            float h01 = fmaxf(c[mt][nt][1] + by, 0.f);
            float h10 = fmaxf(c[mt][nt][2] + bx, 0.f);
            float h11 = fmaxf(c[mt][nt][3] + by, 0.f);
            if (r0 < NN) *(float2*)(d_h + (size_t)r0 * HH + col) = make_float2(h00, h01);
            if (r1 < NN) *(float2*)(d_h + (size_t)r1 * HH + col) = make_float2(h10, h11);
            float wr0 = wrs[col], wr1 = wrs[col + 1];
            float wo0 = wos[col], wo1 = wos[col + 1];
            pr0 += h00 * wr0 + h01 * wr1;  po0 += h00 * wo0 + h01 * wo1;
            pr1 += h10 * wr0 + h11 * wr1;  po1 += h10 * wo0 + h11 * wo1;
        }
        pr0 += __shfl_xor_sync(0xffffffffu, pr0, 1);
        pr0 += __shfl_xor_sync(0xffffffffu, pr0, 2);
        po0 += __shfl_xor_sync(0xffffffffu, po0, 1);
        po0 += __shfl_xor_sync(0xffffffffu, po0, 2);
        pr1 += __shfl_xor_sync(0xffffffffu, pr1, 1);
        pr1 += __shfl_xor_sync(0xffffffffu, pr1, 2);
        po1 += __shfl_xor_sync(0xffffffffu, po1, 1);
        po1 += __shfl_xor_sync(0xffffffffu, po1, 2);
        if ((lane & 3) == 0) {
            if (r0 < NN) { atomicAdd(&d_r[r0], pr0); atomicAdd(&d_root[r0], po0); }
            if (r1 < NN) { atomicAdd(&d_r[r1], pr1); atomicAdd(&d_root[r1], po1); }
        }
    }
}

// ---------------- fused score + per-graph top-K (bitonic) + tanh-gated max pool ----------------
__global__ __launch_bounds__(512) void k_pool(const float* __restrict__ brel,
                                              float* __restrict__ out) {
    __shared__ float ss[1024];
    __shared__ int   si[1024];
    __shared__ float red[512];
    int b = blockIdx.x, t = threadIdx.x;
    float brel0 = brel[0];
    // compute scores for this graph's 1000 nodes
    for (int i = t; i < NPGc; i += 512) {
        int n = b * NPGc + i;
        float sc = brel0 + d_root[n];
        int e0 = d_rowptr[n], e1 = d_rowptr[n + 1];
        for (int e = e0; e < e1; e++) sc += d_r[d_col[e]];
        ss[i] = sc; si[i] = i;
    }
    for (int i = NPGc + t; i < 1024; i += 512) { ss[i] = -INFINITY; si[i] = 0x7fffffff; }
    __syncthreads();
    for (int k = 2; k <= 1024; k <<= 1) {
        for (int j = k >> 1; j > 0; j >>= 1) {
            #pragma unroll
            for (int half = 0; half < 2; half++) {
                int i = t + half * 512;
                int ixj = i ^ j;
                if (ixj > i) {
                    float s1 = ss[i], s2 = ss[ixj];
                    int   i1 = si[i], i2 = si[ixj];
                    bool up  = ((i & k) == 0);
                    bool b21 = (s2 > s1) || (s2 == s1 && i2 < i1);
                    bool b12 = (s1 > s2) || (s1 == s2 && i1 < i2);
                    if (up ? b21 : b12) {
                        ss[i] = s2; ss[ixj] = s1;
                        si[i] = i2; si[ixj] = i1;
                    }
                }
            }
            __syncthreads();
        }
    }
    for (int i = t; i < KSEL; i += 512) ss[i] = tanhf(ss[i]);
    __syncthreads();
    int part = t >> 8, f = t & 255;
    float m = -INFINITY;
    int j0 = part * (KSEL / 2), j1 = j0 + (KSEL / 2);
    for (int j = j0; j < j1; j++) {
        int node = b * NPGc + si[j];
        m = fmaxf(m, d_h[(size_t)node * HH + f] * ss[j]);
    }
    red[t] = m;
    __syncthreads();
    if (part == 0) out[b * HH + f] = fmaxf(red[t], red[t + 256]);
}

// ---------------- launch ----------------
extern "C" void kernel_launch(void* const* d_in, const int* in_sizes, int n_in,
                              void* d_out, int out_size) {
    const int*   x     = (const int*)d_in[0];
    const int*   ei    = (const int*)d_in[1];
    const float* W1    = (const float*)d_in[3];
    const float* b1    = (const float*)d_in[4];
    const float* W2    = (const float*)d_in[5];
    const float* b2    = (const float*)d_in[6];
    const float* Wrel  = (const float*)d_in[7];
    const float* brel  = (const float*)d_in[8];
    const float* Wroot = (const float*)d_in[9];
    float* out = (float*)d_out;
    const int* src = ei;
    const int* dst = ei + EE;

    cudaFuncSetAttribute(k_gemm, cudaFuncAttributeMaxDynamicSharedMemorySize, GEMM_SMEM);
    cudaFuncSetAttribute(k_agg,  cudaFuncAttributeMaxDynamicSharedMemorySize, AGG_SMEM);

    k_zero   <<<SCB, 256>>>();
    k_hist   <<<(EE + 255) / 256, 256>>>(dst, W2);
    k_scan   <<<SCB, 256>>>();
    k_scatter<<<(EE + 255) / 256, 256>>>(src, dst);
    k_layer1 <<<(NN + 7) / 8, 256>>>(x, W1, b1);
    k_agg    <<<dim3(4, BB), 512, AGG_SMEM>>>();
    k_gemm   <<<dim3((NN + 127) / 128, 2), 256, GEMM_SMEM>>>(b2, Wrel, Wroot);
    k_pool   <<<BB, 512>>>(brel, out);
}

// round 9
// speedup vs baseline: 1.3677x; 1.3677x over previous
#include <cuda_runtime.h>
#include <cuda_fp16.h>
#include <math.h>
#include <stdint.h>

#define NN   50000
#define BB   50
#define NPGc 1000
#define EE   300000
#define HH   256
#define KSEL 500
#define SCB  196           // ceil(NN/256) scan blocks

// ---------------- scratch (static device globals; no allocation) ----------------
__device__ __half d_h1h[NN * HH];    // layer1 output, fp16
__device__ __half d_gh [NN * HH];    // aggregated h1, fp16 (GEMM A)
__device__ __half d_w2t[HH * HH];    // W2^T [n][k], fp16 (GEMM B)
__device__ float  d_h  [NN * HH];    // layer2 output, fp32
__device__ int    d_indeg[NN];
__device__ int    d_rowptr[NN + 1];
__device__ int    d_fill[NN];
__device__ int    d_col[EE];
__device__ float  d_dinv[NN];
__device__ float  d_r[NN];
__device__ float  d_root[NN];
__device__ float  d_score[NN];
__device__ unsigned long long d_state[SCB];   // lookback state: flag<<32 | value

// ---------------- helpers ----------------
__device__ __forceinline__ uint32_t smem_u32(const void* p) {
    uint32_t a;
    asm("{ .reg .u64 t; cvta.to.shared.u64 t, %1; cvt.u32.u64 %0, t; }" : "=r"(a) : "l"(p));
    return a;
}
__device__ __forceinline__ void cpa16(uint32_t dst, const void* src, int srcsz) {
    asm volatile("cp.async.ca.shared.global [%0], [%1], 16, %2;"
                 :: "r"(dst), "l"(src), "r"(srcsz));
}
#define CPA_COMMIT() asm volatile("cp.async.commit_group;" ::: "memory")
#define CPA_WAIT(n)  asm volatile("cp.async.wait_group %0;" :: "n"(n) : "memory")

// ---------------- init ----------------
__global__ void k_zero() {
    int i = blockIdx.x * blockDim.x + threadIdx.x;
    if (i < NN) d_indeg[i] = 0;
    if (i < SCB) d_state[i] = 0ull;
}

// ---------------- histogram + W2 transpose fold ----------------
__global__ void k_hist(const int* __restrict__ dst, const float* __restrict__ W2) {
    int t = threadIdx.x;
    int i = blockIdx.x * blockDim.x + t;
    if (i < EE) atomicAdd(&d_indeg[dst[i]], 1);
    int n = blockIdx.x;
    if (n < HH) d_w2t[n * HH + t] = __float2half_rn(W2[t * HH + n]);
}

// ---------------- single-pass decoupled-lookback exclusive scan ----------------
// Also: dinv = rsqrt(indeg+1), zero d_fill / d_r / d_root, rowptr[NN] = EE.
__global__ __launch_bounds__(256) void k_scan() {
    __shared__ int ws[8];
    __shared__ int s_prefix;
    int t = threadIdx.x, lane = t & 31, wid = t >> 5;
    int b = blockIdx.x;
    int i = b * 256 + t;
    int v = (i < NN) ? d_indeg[i] : 0;
    int s = v;
    #pragma unroll
    for (int o = 1; o < 32; o <<= 1) {
        int n = __shfl_up_sync(0xffffffffu, s, o);
        if (lane >= o) s += n;
    }
    if (lane == 31) ws[wid] = s;
    __syncthreads();
    if (wid == 0 && lane < 8) {
        int x = ws[lane];
        #pragma unroll
        for (int o = 1; o < 8; o <<= 1) {
            int n = __shfl_up_sync(0xffu, x, o);
            if (lane >= o) x += n;
        }
        ws[lane] = x;
    }
    __syncthreads();
    int lexcl = s - v + (wid > 0 ? ws[wid - 1] : 0);
    int total = ws[7];

    if (t == 0) {
        if (b == 0) {
            *(volatile unsigned long long*)&d_state[0] =
                (2ull << 32) | (unsigned long long)(unsigned)total;
            s_prefix = 0;
        } else {
            *(volatile unsigned long long*)&d_state[b] =
                (1ull << 32) | (unsigned long long)(unsigned)total;
            int sum = 0;
            int j = b - 1;
            while (1) {
                unsigned long long st;
                do { st = *(volatile unsigned long long*)&d_state[j]; } while ((st >> 32) == 0ull);
                sum += (int)(unsigned)st;
                if ((st >> 32) == 2ull) break;
                j--;
            }
            *(volatile unsigned long long*)&d_state[b] =
                (2ull << 32) | (unsigned long long)(unsigned)(sum + total);
            s_prefix = sum;
        }
    }
    __syncthreads();
    int prefix = s_prefix;
    if (i < NN) {
        d_rowptr[i] = prefix + lexcl;
        d_dinv[i]   = rsqrtf((float)(v + 1));
        d_fill[i]   = 0;
        d_r[i]      = 0.f;
        d_root[i]   = 0.f;
    }
    if (b == SCB - 1 && t == 0) d_rowptr[NN] = EE;
}

__global__ void k_scatter(const int* __restrict__ src, const int* __restrict__ dst) {
    int i = blockIdx.x * blockDim.x + threadIdx.x;
    if (i < EE) {
        int d = dst[i];
        int p = d_rowptr[d] + atomicAdd(&d_fill[d], 1);
        d_col[p] = src[i];
    }
}

// ---------------- layer 1: onehot-gather GCN conv, lane-parallel edge prefetch ----------------
__global__ __launch_bounds__(256) void k_layer1(const int* __restrict__ x,
                                                const float* __restrict__ W1,
                                                const float* __restrict__ b1) {
    int node = (blockIdx.x * blockDim.x + threadIdx.x) >> 5;
    int lane = threadIdx.x & 31;
    if (node >= NN) return;
    float dd = d_dinv[node];
    float a[8];
    {
        const float4* p = (const float4*)(W1 + (size_t)x[node] * HH) + lane * 2;
        float4 v0 = p[0], v1 = p[1];
        a[0] = dd * v0.x; a[1] = dd * v0.y; a[2] = dd * v0.z; a[3] = dd * v0.w;
        a[4] = dd * v1.x; a[5] = dd * v1.y; a[6] = dd * v1.z; a[7] = dd * v1.w;
    }
    int beg = d_rowptr[node], end = d_rowptr[node + 1];
    for (int eb = beg; eb < end; eb += 32) {
        int n = min(32, end - eb);
        int si = 0, xi = 0; float wi = 0.f;
        if (lane < n) { si = d_col[eb + lane]; wi = d_dinv[si]; xi = x[si]; }
        for (int e = 0; e < n; e++) {
            int   xe = __shfl_sync(0xffffffffu, xi, e);
            float we = __shfl_sync(0xffffffffu, wi, e);
            const float4* p = (const float4*)(W1 + (size_t)xe * HH) + lane * 2;
            float4 v0 = p[0], v1 = p[1];
            a[0] += we * v0.x; a[1] += we * v0.y; a[2] += we * v0.z; a[3] += we * v0.w;
            a[4] += we * v1.x; a[5] += we * v1.y; a[6] += we * v1.z; a[7] += we * v1.w;
        }
    }
    const float4* b4 = (const float4*)b1 + lane * 2;
    float4 c0 = b4[0], c1 = b4[1];
    float o[8];
    o[0] = fmaxf(dd * a[0] + c0.x, 0.f); o[1] = fmaxf(dd * a[1] + c0.y, 0.f);
    o[2] = fmaxf(dd * a[2] + c0.z, 0.f); o[3] = fmaxf(dd * a[3] + c0.w, 0.f);
    o[4] = fmaxf(dd * a[4] + c1.x, 0.f); o[5] = fmaxf(dd * a[5] + c1.y, 0.f);
    o[6] = fmaxf(dd * a[6] + c1.z, 0.f); o[7] = fmaxf(dd * a[7] + c1.w, 0.f);
    uint4 pk;
    ((__half2*)&pk)[0] = __floats2half2_rn(o[0], o[1]);
    ((__half2*)&pk)[1] = __floats2half2_rn(o[2], o[3]);
    ((__half2*)&pk)[2] = __floats2half2_rn(o[4], o[5]);
    ((__half2*)&pk)[3] = __floats2half2_rn(o[6], o[7]);
    ((uint4*)(d_h1h + (size_t)node * HH))[lane] = pk;
}

// ---------------- layer 2 aggregation (A-hat * h1), warp per node, fp16 in/out ----------------
__global__ __launch_bounds__(256) void k_agg() {
    int node = (blockIdx.x * blockDim.x + threadIdx.x) >> 5;
    int lane = threadIdx.x & 31;
    if (node >= NN) return;
    float dd = d_dinv[node];
    float a[8];
    {
        uint4 v = ((const uint4*)(d_h1h + (size_t)node * HH))[lane];
        #pragma unroll
        for (int j = 0; j < 4; j++) {
            float2 f = __half22float2(((__half2*)&v)[j]);
            a[2*j]   = dd * f.x;
            a[2*j+1] = dd * f.y;
        }
    }
    int beg = d_rowptr[node], end = d_rowptr[node + 1];
    for (int eb = beg; eb < end; eb += 32) {
        int n = min(32, end - eb);
        int si = 0; float wi = 0.f;
        if (lane < n) { si = d_col[eb + lane]; wi = d_dinv[si]; }
        for (int e = 0; e < n; e++) {
            int   se = __shfl_sync(0xffffffffu, si, e);
            float we = __shfl_sync(0xffffffffu, wi, e);
            uint4 v = ((const uint4*)(d_h1h + (size_t)se * HH))[lane];
            #pragma unroll
            for (int j = 0; j < 4; j++) {
                float2 f = __half22float2(((__half2*)&v)[j]);
                a[2*j]   += we * f.x;
                a[2*j+1] += we * f.y;
            }
        }
    }
    uint4 pk;
    #pragma unroll
    for (int j = 0; j < 4; j++)
        ((__half2*)&pk)[j] = __floats2half2_rn(dd * a[2*j], dd * a[2*j+1]);
    ((uint4*)(d_gh + (size_t)node * HH))[lane] = pk;
}

// ---------------- GEMM: h = relu(g @ W2 + b2) via fp16 mma m16n8k16, fused scorer ----------------
#define SROWH 40
#define STGH  (128 * SROWH)
#define GEMM_SMEM (4 * STGH * 2 + 3 * HH * 4)

__global__ __launch_bounds__(256) void k_gemm(const float* __restrict__ b2,
                                              const float* __restrict__ Wrel,
                                              const float* __restrict__ Wroot) {
    extern __shared__ __align__(16) char smc[];
    __half* sA = (__half*)smc;
    __half* sB = sA + 2 * STGH;
    float*  b2s = (float*)(sB + 2 * STGH);
    float*  wrs = b2s + HH;
    float*  wos = wrs + HH;
    uint32_t sA_u = smem_u32(sA), sB_u = smem_u32(sB);

    int tid = threadIdx.x, lane = tid & 31, warpId = tid >> 5;
    int warp_m = warpId & 1, warp_n = warpId >> 1;
    int rowBase = blockIdx.x * 128;
    int colBase = blockIdx.y * 128;

    for (int i = tid; i < HH; i += 256) { b2s[i] = b2[i]; wrs[i] = Wrel[i]; wos[i] = Wroot[i]; }

    float c[4][4][4];
    #pragma unroll
    for (int mt = 0; mt < 4; mt++)
        #pragma unroll
        for (int nt = 0; nt < 4; nt++)
            #pragma unroll
            for (int q = 0; q < 4; q++) c[mt][nt][q] = 0.f;

    int cprow = tid >> 1, cpc = (tid & 1) * 2;
    #define PREFETCH(s) do {                                                         \
        int buf = (s) & 1;                                                           \
        int gr = rowBase + cprow;                                                    \
        int sz = (gr < NN) ? 16 : 0;                                                 \
        int grc = (gr < NN) ? gr : 0;                                                \
        int nrow = colBase + cprow;                                                  \
        _Pragma("unroll")                                                            \
        for (int h = 0; h < 2; h++) {                                                \
            int cc = cpc + h;                                                        \
            cpa16(sA_u + (uint32_t)(buf * STGH + cprow * SROWH + cc * 8) * 2,        \
                  d_gh + (size_t)grc * HH + (s) * 32 + cc * 8, sz);                  \
            cpa16(sB_u + (uint32_t)(buf * STGH + cprow * SROWH + cc * 8) * 2,        \
                  d_w2t + (size_t)nrow * HH + (s) * 32 + cc * 8, 16);                \
        }                                                                            \
    } while (0)

    PREFETCH(0); CPA_COMMIT();

    int fc = lane & 3, fr = lane >> 2;
    for (int s = 0; s < 8; s++) {
        if (s < 7) { PREFETCH(s + 1); CPA_COMMIT(); CPA_WAIT(1); }
        else       { CPA_WAIT(0); }
        __syncthreads();
        const __half* A = sA + (s & 1) * STGH;
        const __half* B = sB + (s & 1) * STGH;
        #pragma unroll
        for (int ks = 0; ks < 2; ks++) {
            uint32_t a0[4], a1[4], a2[4], a3[4], b0[4], b1[4];
            #pragma unroll
            for (int mt = 0; mt < 4; mt++) {
                int mr = warp_m * 64 + mt * 16 + fr;
                const __half* pa  = A + mr * SROWH + ks * 16 + fc * 2;
                const __half* pa8 = pa + 8 * SROWH;
                a0[mt] = *(const uint32_t*)pa;
                a2[mt] = *(const uint32_t*)(pa + 8);
                a1[mt] = *(const uint32_t*)pa8;
                a3[mt] = *(const uint32_t*)(pa8 + 8);
            }
            #pragma unroll
            for (int nt = 0; nt < 4; nt++) {
                int nr = warp_n * 32 + nt * 8 + fr;
                const __half* pb = B + nr * SROWH + ks * 16 + fc * 2;
                b0[nt] = *(const uint32_t*)pb;
                b1[nt] = *(const uint32_t*)(pb + 8);
            }
            #pragma unroll
            for (int mt = 0; mt < 4; mt++)
                #pragma unroll
                for (int nt = 0; nt < 4; nt++) {
                    asm volatile(
                        "mma.sync.aligned.m16n8k16.row.col.f32.f16.f16.f32 "
                        "{%0,%1,%2,%3}, {%4,%5,%6,%7}, {%8,%9}, {%0,%1,%2,%3};"
                        : "+f"(c[mt][nt][0]), "+f"(c[mt][nt][1]),
                          "+f"(c[mt][nt][2]), "+f"(c[mt][nt][3])
                        : "r"(a0[mt]), "r"(a1[mt]), "r"(a2[mt]), "r"(a3[mt]),
                          "r"(b0[nt]), "r"(b1[nt]));
                }
        }
        __syncthreads();
    }

    #pragma unroll
    for (int mt = 0; mt < 4; mt++) {
        int r0 = rowBase + warp_m * 64 + mt * 16 + (lane >> 2);
        int r1 = r0 + 8;
        float pr0 = 0.f, po0 = 0.f, pr1 = 0.f, po1 = 0.f;
        #pragma unroll
        for (int nt = 0; nt < 4; nt++) {
            int col = colBase + warp_n * 32 + nt * 8 + 2 * (lane & 3);
            float bx = b2s[col], by = b2s[col + 1];
            float h00 = fmaxf(c[mt][nt][0] + bx, 0.f);
            float h01 = fmaxf(c[mt][nt][1] + by, 0.f);
            float h10 = fmaxf(c[mt][nt][2] + bx, 0.f);
            float h11 = fmaxf(c[mt][nt][3] + by, 0.f);
            if (r0 < NN) *(float2*)(d_h + (size_t)r0 * HH + col) = make_float2(h00, h01);
            if (r1 < NN) *(float2*)(d_h + (size_t)r1 * HH + col) = make_float2(h10, h11);
            float wr0 = wrs[col], wr1 = wrs[col + 1];
            float wo0 = wos[col], wo1 = wos[col + 1];
            pr0 += h00 * wr0 + h01 * wr1;  po0 += h00 * wo0 + h01 * wo1;
            pr1 += h10 * wr0 + h11 * wr1;  po1 += h10 * wo0 + h11 * wo1;
        }
        pr0 += __shfl_xor_sync(0xffffffffu, pr0, 1);
        pr0 += __shfl_xor_sync(0xffffffffu, pr0, 2);
        po0 += __shfl_xor_sync(0xffffffffu, po0, 1);
        po0 += __shfl_xor_sync(0xffffffffu, po0, 2);
        pr1 += __shfl_xor_sync(0xffffffffu, pr1, 1);
        pr1 += __shfl_xor_sync(0xffffffffu, pr1, 2);
        po1 += __shfl_xor_sync(0xffffffffu, po1, 1);
        po1 += __shfl_xor_sync(0xffffffffu, po1, 2);
        if ((lane & 3) == 0) {
            if (r0 < NN) { atomicAdd(&d_r[r0], pr0); atomicAdd(&d_root[r0], po0); }
            if (r1 < NN) { atomicAdd(&d_r[r1], pr1); atomicAdd(&d_root[r1], po1); }
        }
    }
}

// ---------------- score: brel + root + sum_{edges} r[src] ----------------
__global__ void k_score(const float* __restrict__ brel) {
    int i = blockIdx.x * blockDim.x + threadIdx.x;
    if (i >= NN) return;
    float sc = brel[0] + d_root[i];
    int beg = d_rowptr[i], end = d_rowptr[i + 1];
    for (int e = beg; e < end; e++) sc += d_r[d_col[e]];
    d_score[i] = sc;
}

// ---------------- per-graph top-K (bitonic) + tanh-gated global max pool ----------------
__global__ __launch_bounds__(512) void k_pool(float* __restrict__ out) {
    __shared__ float ss[1024];
    __shared__ int   si[1024];
    __shared__ float red[512];
    int b = blockIdx.x, t = threadIdx.x;
    for (int i = t; i < 1024; i += 512) {
        if (i < NPGc) { ss[i] = d_score[b * NPGc + i]; si[i] = i; }
        else          { ss[i] = -INFINITY;             si[i] = 0x7fffffff; }
    }
    __syncthreads();
    for (int k = 2; k <= 1024; k <<= 1) {
        for (int j = k >> 1; j > 0; j >>= 1) {
            #pragma unroll
            for (int half = 0; half < 2; half++) {
                int i = t + half * 512;
                int ixj = i ^ j;
                if (ixj > i) {
                    float s1 = ss[i], s2 = ss[ixj];
                    int   i1 = si[i], i2 = si[ixj];
                    bool up  = ((i & k) == 0);
                    bool b21 = (s2 > s1) || (s2 == s1 && i2 < i1);
                    bool b12 = (s1 > s2) || (s1 == s2 && i1 < i2);
                    if (up ? b21 : b12) {
                        ss[i] = s2; ss[ixj] = s1;
                        si[i] = i2; si[ixj] = i1;
                    }
                }
            }
            __syncthreads();
        }
    }
    for (int i = t; i < KSEL; i += 512) ss[i] = tanhf(ss[i]);
    __syncthreads();
    int part = t >> 8, f = t & 255;
    float m = -INFINITY;
    int j0 = part * (KSEL / 2), j1 = j0 + (KSEL / 2);
    for (int j = j0; j < j1; j++) {
        int node = b * NPGc + si[j];
        m = fmaxf(m, d_h[(size_t)node * HH + f] * ss[j]);
    }
    red[t] = m;
    __syncthreads();
    if (part == 0) out[b * HH + f] = fmaxf(red[t], red[t + 256]);
}

// ---------------- launch ----------------
extern "C" void kernel_launch(void* const* d_in, const int* in_sizes, int n_in,
                              void* d_out, int out_size) {
    const int*   x     = (const int*)d_in[0];
    const int*   ei    = (const int*)d_in[1];
    const float* W1    = (const float*)d_in[3];
    const float* b1    = (const float*)d_in[4];
    const float* W2    = (const float*)d_in[5];
    const float* b2    = (const float*)d_in[6];
    const float* Wrel  = (const float*)d_in[7];
    const float* brel  = (const float*)d_in[8];
    const float* Wroot = (const float*)d_in[9];
    float* out = (float*)d_out;
    const int* src = ei;
    const int* dst = ei + EE;

    cudaFuncSetAttribute(k_gemm, cudaFuncAttributeMaxDynamicSharedMemorySize, GEMM_SMEM);

    k_zero   <<<SCB, 256>>>();
    k_hist   <<<(EE + 255) / 256, 256>>>(dst, W2);
    k_scan   <<<SCB, 256>>>();
    k_scatter<<<(EE + 255) / 256, 256>>>(src, dst);
    k_layer1 <<<(NN + 7) / 8, 256>>>(x, W1, b1);
    k_agg    <<<(NN + 7) / 8, 256>>>();
    k_gemm   <<<dim3((NN + 127) / 128, 2), 256, GEMM_SMEM>>>(b2, Wrel, Wroot);
    k_score  <<<(NN + 255) / 256, 256>>>(brel);
    k_pool   <<<BB, 512>>>(out);
}